// round 3
// baseline (speedup 1.0000x reference)
#include <cuda_runtime.h>

#define Bb 8
#define Ll 512
#define Dd 256
#define Uu 32
#define TS 8       // s-rows per block in the fused kernel
#define PAD 12     // padded row stride (floats) of transposed weight tile [t][s]

// scratch: Eq = exp2(C*(q+bh)) and Ek = exp2(C*k), [B*L, U], C = 2*log2(e)
__device__ float g_q[Bb * Ll * Uu];
__device__ float g_k[Bb * Ll * Uu];

__device__ __forceinline__ float fast_ex2(float x) {
    float y; asm("ex2.approx.f32 %0, %1;" : "=f"(y) : "f"(x)); return y;
}
__device__ __forceinline__ float fast_rcp(float x) {
    float y; asm("rcp.approx.f32 %0, %1;" : "=f"(y) : "f"(x)); return y;
}
__device__ __forceinline__ unsigned long long pack2(float lo, float hi) {
    unsigned long long r;
    asm("mov.b64 %0, {%1, %2};" : "=l"(r) : "f"(lo), "f"(hi));
    return r;
}
__device__ __forceinline__ void unpack2(float& lo, float& hi, unsigned long long v) {
    asm("mov.b64 {%0, %1}, %2;" : "=f"(lo), "=f"(hi) : "l"(v));
}
__device__ __forceinline__ void fma2(unsigned long long& d, unsigned long long a,
                                     unsigned long long b) {
    asm("fma.rn.f32x2 %0, %1, %2, %0;" : "+l"(d) : "l"(a), "l"(b));
}

// ---------------------------------------------------------------------------
// Kernel 1 (f32x2 over u-pairs):
//   Eq[row,u] = exp2(C*(bh[u] + x[row,:]·Wt[:,u]))
//   Ek[row,u] = exp2(C*(x[row,:]·Wx[:,u]))
// 8 rows/block, 256 threads = (u-pair:16) x (q/k:2) x (row:8)
// ---------------------------------------------------------------------------
__global__ __launch_bounds__(256) void qk_kernel(const float* __restrict__ x,
                                                 const float* __restrict__ Wt,
                                                 const float* __restrict__ Wx,
                                                 const float* __restrict__ bh) {
    __shared__ float xs[8 * Dd];
    const int row0 = blockIdx.x * 8;

    const float4* xg = (const float4*)(x + (size_t)row0 * Dd);
    float4* xs4 = (float4*)xs;
    xs4[threadIdx.x] = xg[threadIdx.x];
    xs4[threadIdx.x + 256] = xg[threadIdx.x + 256];
    __syncthreads();

    const int up = (threadIdx.x & 15) * 2;      // u pair base: 0,2,..,30
    const int which = (threadIdx.x >> 4) & 1;   // 0 -> q (Wt,+bh), 1 -> k (Wx)
    const int row = threadIdx.x >> 5;           // 0..7 (warp-uniform)
    const float* __restrict__ W = which ? Wx : Wt;

    unsigned long long acc =
        which ? 0ull : pack2(bh[up], bh[up + 1]);

    const float* xr = xs + row * Dd;
#pragma unroll 4
    for (int d = 0; d < Dd; d++) {
        unsigned long long ww = *(const unsigned long long*)(W + d * Uu + up);
        float xv = xr[d];                       // smem broadcast within warp
        fma2(acc, ww, pack2(xv, xv));
    }

    const float C2LOG2E = 2.8853900817779268f;  // 2*log2(e)
    float lo, hi;
    unpack2(lo, hi, acc);
    float* dst = (which ? g_k : g_q) + (size_t)(row0 + row) * Uu + up;
    dst[0] = fast_ex2(C2LOG2E * lo);
    dst[1] = fast_ex2(C2LOG2E * hi);
}

// ---------------------------------------------------------------------------
// Kernel 2 (fused), 256 threads, TS=8 s-rows, grid = 512 blocks:
//   A: alpha[s,t] = sumWa - 2*sum_u Wa_u / (1 + Eq[s,u]*Ek[t,u])
//   B: softmax over t (per s row)
//   C: c[s,:] = sum_t a[s,t] * x[b,t,:]   (packed f32x2 FFMA)
// Weight tile stored transposed sa[t][s], stride PAD (48B, 16B-aligned).
// ---------------------------------------------------------------------------
__global__ __launch_bounds__(256, 4) void attn_kernel(const float* __restrict__ x,
                                                      const float* __restrict__ Wa,
                                                      float* __restrict__ out) {
    __shared__ float sa[Ll * PAD];  // 24 KB
    __shared__ float sq[TS * Uu];   // 1 KB
    __shared__ float swa[Uu];

    const int tid = threadIdx.x;
    const int b = blockIdx.x >> 6;
    const int s0 = (blockIdx.x & 63) * TS;

    sq[tid] = g_q[((size_t)b * Ll + s0) * Uu + tid];   // 256 = TS*Uu exactly
    if (tid < Uu) swa[tid] = Wa[tid];
    __syncthreads();

    float sumwa = 0.f;
#pragma unroll
    for (int u = 0; u < Uu; u++) sumwa += swa[u];

    // -------- Phase A: thread handles key rows t = tid and tid+256
#pragma unroll
    for (int tr = 0; tr < 2; tr++) {
        const int t = tid + 256 * tr;
        float kk[32];
        const float4* kg = (const float4*)(g_k + ((size_t)b * Ll + t) * Uu);
#pragma unroll
        for (int i = 0; i < 8; i++) {
            float4 kv = kg[i];
            kk[4 * i + 0] = kv.x; kk[4 * i + 1] = kv.y;
            kk[4 * i + 2] = kv.z; kk[4 * i + 3] = kv.w;
        }

        float acc[TS];
#pragma unroll
        for (int s = 0; s < TS; s++) acc[s] = 0.f;

#pragma unroll
        for (int i = 0; i < 8; i++) {
            float4 w4 = ((const float4*)swa)[i];
#pragma unroll
            for (int s = 0; s < TS; s++) {
                float4 q4 = ((const float4*)(sq + s * Uu))[i];  // broadcast LDS
                acc[s] = fmaf(w4.x, fast_rcp(fmaf(kk[4 * i + 0], q4.x, 1.f)), acc[s]);
                acc[s] = fmaf(w4.y, fast_rcp(fmaf(kk[4 * i + 1], q4.y, 1.f)), acc[s]);
                acc[s] = fmaf(w4.z, fast_rcp(fmaf(kk[4 * i + 2], q4.z, 1.f)), acc[s]);
                acc[s] = fmaf(w4.w, fast_rcp(fmaf(kk[4 * i + 3], q4.w, 1.f)), acc[s]);
            }
        }
#pragma unroll
        for (int s = 0; s < TS; s++)
            sa[t * PAD + s] = fmaf(-2.f, acc[s], sumwa);
    }
    __syncthreads();

    // -------- Phase B: warp w handles softmax of row s = w (8 warps)
    {
        const int w = tid >> 5;
        const int lane = tid & 31;
        const float LOG2E = 1.4426950408889634f;

        float v[16];
        float m = -1e30f;
#pragma unroll
        for (int i = 0; i < 16; i++) {
            v[i] = sa[(lane + 32 * i) * PAD + w];
            m = fmaxf(m, v[i]);
        }
#pragma unroll
        for (int off = 16; off > 0; off >>= 1)
            m = fmaxf(m, __shfl_xor_sync(0xffffffffu, m, off));

        float ssum = 0.f;
#pragma unroll
        for (int i = 0; i < 16; i++) {
            v[i] = fast_ex2((v[i] - m) * LOG2E);
            ssum += v[i];
        }
#pragma unroll
        for (int off = 16; off > 0; off >>= 1)
            ssum += __shfl_xor_sync(0xffffffffu, ssum, off);

        const float inv = fast_rcp(ssum);
#pragma unroll
        for (int i = 0; i < 16; i++) sa[(lane + 32 * i) * PAD + w] = v[i] * inv;
    }
    __syncthreads();

    // -------- Phase C: thread owns column d = tid, all 8 s-rows
    // (4 f32x2 accumulators over consecutive-s pairs)
    {
        const int d = tid;
        unsigned long long acc0 = 0ull, acc1 = 0ull, acc2 = 0ull, acc3 = 0ull;
        const float* __restrict__ xb = x + (size_t)b * Ll * Dd + d;

        for (int t = 0; t < Ll; t += 4) {
            float x0 = xb[(t + 0) * Dd];
            float x1 = xb[(t + 1) * Dd];
            float x2 = xb[(t + 2) * Dd];
            float x3 = xb[(t + 3) * Dd];

            ulonglong2 a0 = *(const ulonglong2*)(sa + (t + 0) * PAD);      // s0..3
            ulonglong2 b0 = *(const ulonglong2*)(sa + (t + 0) * PAD + 4);  // s4..7
            ulonglong2 a1 = *(const ulonglong2*)(sa + (t + 1) * PAD);
            ulonglong2 b1 = *(const ulonglong2*)(sa + (t + 1) * PAD + 4);
            ulonglong2 a2 = *(const ulonglong2*)(sa + (t + 2) * PAD);
            ulonglong2 b2 = *(const ulonglong2*)(sa + (t + 2) * PAD + 4);
            ulonglong2 a3 = *(const ulonglong2*)(sa + (t + 3) * PAD);
            ulonglong2 b3 = *(const ulonglong2*)(sa + (t + 3) * PAD + 4);

            unsigned long long xx0 = pack2(x0, x0);
            unsigned long long xx1 = pack2(x1, x1);
            unsigned long long xx2 = pack2(x2, x2);
            unsigned long long xx3 = pack2(x3, x3);

            fma2(acc0, a0.x, xx0); fma2(acc1, a0.y, xx0);
            fma2(acc2, b0.x, xx0); fma2(acc3, b0.y, xx0);
            fma2(acc0, a1.x, xx1); fma2(acc1, a1.y, xx1);
            fma2(acc2, b1.x, xx1); fma2(acc3, b1.y, xx1);
            fma2(acc0, a2.x, xx2); fma2(acc1, a2.y, xx2);
            fma2(acc2, b2.x, xx2); fma2(acc3, b2.y, xx2);
            fma2(acc0, a3.x, xx3); fma2(acc1, a3.y, xx3);
            fma2(acc2, b3.x, xx3); fma2(acc3, b3.y, xx3);
        }

        float* ob = out + ((size_t)b * Ll + s0) * Dd + d;
        float lo, hi;
        unpack2(lo, hi, acc0); ob[0 * Dd] = lo; ob[1 * Dd] = hi;
        unpack2(lo, hi, acc1); ob[2 * Dd] = lo; ob[3 * Dd] = hi;
        unpack2(lo, hi, acc2); ob[4 * Dd] = lo; ob[5 * Dd] = hi;
        unpack2(lo, hi, acc3); ob[6 * Dd] = lo; ob[7 * Dd] = hi;
    }
}

// ---------------------------------------------------------------------------
extern "C" void kernel_launch(void* const* d_in, const int* in_sizes, int n_in,
                              void* d_out, int out_size) {
    const float* x  = (const float*)d_in[0];
    const float* Wt = (const float*)d_in[1];
    const float* Wx = (const float*)d_in[2];
    const float* bh = (const float*)d_in[3];
    const float* Wa = (const float*)d_in[4];
    // d_in[5] = ba: uniform shift of alpha -> softmax-invariant, exactly droppable
    float* out = (float*)d_out;

    qk_kernel<<<Bb * Ll / 8, 256>>>(x, Wt, Wx, bh);
    attn_kernel<<<Bb * (Ll / TS), 256>>>(x, Wa, out);
}

// round 7
// speedup vs baseline: 1.7091x; 1.7091x over previous
#include <cuda_runtime.h>

#define Bb 8
#define Ll 512
#define Dd 256
#define Uu 32
#define TS 16      // s-rows per block in the fused kernel
#define PAD 20     // padded row stride (floats) of transposed weight tile [t][s]

// scratch: Eq = exp2(C*(q+bh)) and Ek = exp2(C*k), [B*L, U], C = 2*log2(e)
__device__ float g_q[Bb * Ll * Uu];
__device__ float g_k[Bb * Ll * Uu];

__device__ __forceinline__ float fast_ex2(float x) {
    float y; asm("ex2.approx.f32 %0, %1;" : "=f"(y) : "f"(x)); return y;
}
__device__ __forceinline__ float fast_rcp(float x) {
    float y; asm("rcp.approx.f32 %0, %1;" : "=f"(y) : "f"(x)); return y;
}
__device__ __forceinline__ unsigned long long pack2(float lo, float hi) {
    unsigned long long r;
    asm("mov.b64 %0, {%1, %2};" : "=l"(r) : "f"(lo), "f"(hi));
    return r;
}
__device__ __forceinline__ void unpack2(float& lo, float& hi, unsigned long long v) {
    asm("mov.b64 {%0, %1}, %2;" : "=f"(lo), "=f"(hi) : "l"(v));
}
__device__ __forceinline__ void fma2(unsigned long long& d, unsigned long long a,
                                     unsigned long long b) {
    asm("fma.rn.f32x2 %0, %1, %2, %0;" : "+l"(d) : "l"(a), "l"(b));
}
__device__ __forceinline__ void add2(unsigned long long& d, unsigned long long a) {
    asm("add.rn.f32x2 %0, %0, %1;" : "+l"(d) : "l"(a));
}

// ---------------------------------------------------------------------------
// Kernel 1 (R2 version): q/k projections + exp factoring
//   Eq[row,u] = exp2(C*(bh[u] + x[row,:]·Wt[:,u]))
//   Ek[row,u] = exp2(C*(x[row,:]·Wx[:,u]))
// 8 rows per block, 256 threads: (u:32) x (q/k:2) x (row-pair:4)
// ---------------------------------------------------------------------------
__global__ __launch_bounds__(256) void qk_kernel(const float* __restrict__ x,
                                                 const float* __restrict__ Wt,
                                                 const float* __restrict__ Wx,
                                                 const float* __restrict__ bh) {
    __shared__ float xs[8 * Dd];
    const int row0 = blockIdx.x * 8;

    const float4* xg = (const float4*)(x + (size_t)row0 * Dd);
    float4* xs4 = (float4*)xs;
    xs4[threadIdx.x] = xg[threadIdx.x];
    xs4[threadIdx.x + 256] = xg[threadIdx.x + 256];
    __syncthreads();

    const int u = threadIdx.x & 31;
    const int which = (threadIdx.x >> 5) & 1;  // warp-uniform: 0 -> q, 1 -> k
    const int rp = threadIdx.x >> 6;           // 0..3
    const float* __restrict__ W = which ? Wx : Wt;

    float acc0 = which ? 0.f : bh[u];
    float acc1 = acc0;
    const float* xr0 = xs + rp * Dd;
    const float* xr1 = xs + (rp + 4) * Dd;

#pragma unroll 8
    for (int d = 0; d < Dd; d++) {
        float w = W[d * Uu + u];
        acc0 = fmaf(xr0[d], w, acc0);
        acc1 = fmaf(xr1[d], w, acc1);
    }

    const float C2LOG2E = 2.8853900817779268f;  // 2*log2(e)
    float* dst = which ? g_k : g_q;
    dst[(row0 + rp) * Uu + u] = fast_ex2(C2LOG2E * acc0);
    dst[(row0 + rp + 4) * Uu + u] = fast_ex2(C2LOG2E * acc1);
}

// ---------------------------------------------------------------------------
// Kernel 2 (fused), 512 threads, TS=16, grid = 256 blocks:
//   A: alpha[s,t] = sumWa - 2*sum_u Wa_u / (1 + Eq[s,u]*Ek[t,u])
//   B: softmax over t (per s row)
//   C: c[s,:] = sum_t a[s,t] * x[b,t,:]  -- rank-1 updates, thread owns a
//      d-column and ALL 16 s-rows; thread halves split the t range; smem
//      reduction at the end. Weight LDS are warp-broadcast (conflict-free).
// ---------------------------------------------------------------------------
__global__ __launch_bounds__(512, 2) void attn_kernel(const float* __restrict__ x,
                                                      const float* __restrict__ Wa,
                                                      float* __restrict__ out) {
    __shared__ __align__(16) float sa[Ll * PAD];  // 40 KB: weights [t][s] / reduce buf
    __shared__ __align__(16) float sq[TS * Uu];   // 2 KB
    __shared__ float swa[Uu];

    const int tid = threadIdx.x;
    const int b = blockIdx.x >> 5;        // 32 tiles per batch
    const int s0 = (blockIdx.x & 31) * TS;

    sq[tid] = g_q[((size_t)b * Ll + s0) * Uu + tid];  // 512 = TS*Uu exactly
    if (tid < Uu) swa[tid] = Wa[tid];
    __syncthreads();

    // -------- Phase A: thread `tid` owns key row t = tid
    {
        const int t = tid;
        float kk[32];
        const float4* kg = (const float4*)(g_k + ((size_t)b * Ll + t) * Uu);
#pragma unroll
        for (int i = 0; i < 8; i++) {
            float4 kv = kg[i];
            kk[4 * i + 0] = kv.x; kk[4 * i + 1] = kv.y;
            kk[4 * i + 2] = kv.z; kk[4 * i + 3] = kv.w;
        }

        float sumwa = 0.f;
#pragma unroll
        for (int u = 0; u < Uu; u++) sumwa += swa[u];

        const float4* swa4 = (const float4*)swa;

#pragma unroll
        for (int s = 0; s < TS; s++) {
            const float4* eq4 = (const float4*)(sq + s * Uu);
            float acc0 = 0.f, acc1 = 0.f;
#pragma unroll
            for (int i = 0; i < 8; i++) {
                float4 q4 = eq4[i];   // broadcast LDS
                float4 w4 = swa4[i];
                acc0 = fmaf(w4.x, fast_rcp(fmaf(kk[4 * i + 0], q4.x, 1.f)), acc0);
                acc1 = fmaf(w4.y, fast_rcp(fmaf(kk[4 * i + 1], q4.y, 1.f)), acc1);
                acc0 = fmaf(w4.z, fast_rcp(fmaf(kk[4 * i + 2], q4.z, 1.f)), acc0);
                acc1 = fmaf(w4.w, fast_rcp(fmaf(kk[4 * i + 3], q4.w, 1.f)), acc1);
            }
            sa[t * PAD + s] = fmaf(-2.f, acc0 + acc1, sumwa);
        }
    }
    __syncthreads();

    // -------- Phase B: warp w handles softmax of row s = w (16 warps)
    {
        const int w = tid >> 5;
        const int lane = tid & 31;
        const float LOG2E = 1.4426950408889634f;

        float v[16];
        float m = -1e30f;
#pragma unroll
        for (int i = 0; i < 16; i++) {
            v[i] = sa[(lane + 32 * i) * PAD + w];
            m = fmaxf(m, v[i]);
        }
#pragma unroll
        for (int off = 16; off > 0; off >>= 1)
            m = fmaxf(m, __shfl_xor_sync(0xffffffffu, m, off));

        float ssum = 0.f;
#pragma unroll
        for (int i = 0; i < 16; i++) {
            v[i] = fast_ex2((v[i] - m) * LOG2E);
            ssum += v[i];
        }
#pragma unroll
        for (int off = 16; off > 0; off >>= 1)
            ssum += __shfl_xor_sync(0xffffffffu, ssum, off);

        const float inv = fast_rcp(ssum);
#pragma unroll
        for (int i = 0; i < 16; i++) sa[(lane + 32 * i) * PAD + w] = v[i] * inv;
    }
    __syncthreads();

    // -------- Phase C: thread owns d = tid&255 and all 16 s; halves split t
    {
        const int d = tid & 255;
        const int th = tid >> 8;  // t-half: 0 -> t in [0,256), 1 -> [256,512)
        unsigned long long acc[8];
#pragma unroll
        for (int j = 0; j < 8; j++) acc[j] = 0ull;

        const float* __restrict__ xb = x + ((size_t)b * Ll + th * 256) * Dd + d;
        const float* sp = sa + th * 256 * PAD;

        for (int t = 0; t < 256; t += 2) {
            float xv0 = xb[(t + 0) * Dd];   // coalesced LDG
            float xv1 = xb[(t + 1) * Dd];

            const float* r0 = sp + (t + 0) * PAD;
            const float* r1 = sp + (t + 1) * PAD;
            // warp-broadcast LDS.128 (all lanes read the same address)
            ulonglong2 p0 = *(const ulonglong2*)(r0);
            ulonglong2 p1 = *(const ulonglong2*)(r0 + 4);
            ulonglong2 p2 = *(const ulonglong2*)(r0 + 8);
            ulonglong2 p3 = *(const ulonglong2*)(r0 + 12);
            ulonglong2 q0 = *(const ulonglong2*)(r1);
            ulonglong2 q1 = *(const ulonglong2*)(r1 + 4);
            ulonglong2 q2 = *(const ulonglong2*)(r1 + 8);
            ulonglong2 q3 = *(const ulonglong2*)(r1 + 12);

            unsigned long long xx0 = pack2(xv0, xv0);
            unsigned long long xx1 = pack2(xv1, xv1);

            fma2(acc[0], p0.x, xx0); fma2(acc[1], p0.y, xx0);
            fma2(acc[2], p1.x, xx0); fma2(acc[3], p1.y, xx0);
            fma2(acc[4], p2.x, xx0); fma2(acc[5], p2.y, xx0);
            fma2(acc[6], p3.x, xx0); fma2(acc[7], p3.y, xx0);

            fma2(acc[0], q0.x, xx1); fma2(acc[1], q0.y, xx1);
            fma2(acc[2], q1.x, xx1); fma2(acc[3], q1.y, xx1);
            fma2(acc[4], q2.x, xx1); fma2(acc[5], q2.y, xx1);
            fma2(acc[6], q3.x, xx1); fma2(acc[7], q3.y, xx1);
        }

        __syncthreads();  // all weight reads done; sa reusable as reduce buffer

        // half 1 stores partials: row d, stride 9 u64 (=72B -> 2-way conflicts)
        unsigned long long* red = (unsigned long long*)sa;
        if (th == 1) {
#pragma unroll
            for (int j = 0; j < 8; j++) red[d * 9 + j] = acc[j];
        }
        __syncthreads();

        if (th == 0) {
            float* ob = out + ((size_t)b * Ll + s0) * Dd + d;
#pragma unroll
            for (int j = 0; j < 8; j++) {
                add2(acc[j], red[d * 9 + j]);
                float lo, hi;
                unpack2(lo, hi, acc[j]);
                ob[(2 * j + 0) * Dd] = lo;   // coalesced STG
                ob[(2 * j + 1) * Dd] = hi;
            }
        }
    }
}

// ---------------------------------------------------------------------------
extern "C" void kernel_launch(void* const* d_in, const int* in_sizes, int n_in,
                              void* d_out, int out_size) {
    const float* x  = (const float*)d_in[0];
    const float* Wt = (const float*)d_in[1];
    const float* Wx = (const float*)d_in[2];
    const float* bh = (const float*)d_in[3];
    const float* Wa = (const float*)d_in[4];
    // d_in[5] = ba: uniform shift of alpha -> softmax-invariant, exactly droppable
    float* out = (float*)d_out;

    qk_kernel<<<Bb * Ll / 8, 256>>>(x, Wt, Wx, bh);
    attn_kernel<<<Bb * (Ll / TS), 512>>>(x, Wa, out);
}

// round 9
// speedup vs baseline: 1.9356x; 1.1325x over previous
#include <cuda_runtime.h>

#define Bb 8
#define Ll 512
#define Dd 256
#define Uu 32
#define TS 16      // s-rows per block in the fused kernel
#define PAD 20     // padded row stride (floats) of transposed weight tile [t][s]
#define RSTRIDE 17 // u64 stride of the reduction buffer (bank-conflict pad)

// scratch: Eq = exp2(C*(q+bh)) and Ek = exp2(C*k), [B*L, U], C = 2*log2(e)
__device__ float g_q[Bb * Ll * Uu];
__device__ float g_k[Bb * Ll * Uu];

__device__ __forceinline__ float fast_ex2(float x) {
    float y; asm("ex2.approx.f32 %0, %1;" : "=f"(y) : "f"(x)); return y;
}
__device__ __forceinline__ float fast_rcp(float x) {
    float y; asm("rcp.approx.f32 %0, %1;" : "=f"(y) : "f"(x)); return y;
}
__device__ __forceinline__ unsigned long long pack2(float lo, float hi) {
    unsigned long long r;
    asm("mov.b64 %0, {%1, %2};" : "=l"(r) : "f"(lo), "f"(hi));
    return r;
}
__device__ __forceinline__ void unpack2(float& lo, float& hi, unsigned long long v) {
    asm("mov.b64 {%0, %1}, %2;" : "=f"(lo), "=f"(hi) : "l"(v));
}
__device__ __forceinline__ void fma2(unsigned long long& d, unsigned long long a,
                                     unsigned long long b) {
    asm("fma.rn.f32x2 %0, %1, %2, %0;" : "+l"(d) : "l"(a), "l"(b));
}
__device__ __forceinline__ void add2(unsigned long long& d, unsigned long long a) {
    asm("add.rn.f32x2 %0, %0, %1;" : "+l"(d) : "l"(a));
}

// ---------------------------------------------------------------------------
// Kernel 1: q/k projections + exp factoring
//   Eq[row,u] = exp2(C*(bh[u] + x[row,:]·Wt[:,u]))
//   Ek[row,u] = exp2(C*(x[row,:]·Wx[:,u]))
// 8 rows per block, 256 threads: (u:32) x (q/k:2) x (row-pair:4)
// ---------------------------------------------------------------------------
__global__ __launch_bounds__(256) void qk_kernel(const float* __restrict__ x,
                                                 const float* __restrict__ Wt,
                                                 const float* __restrict__ Wx,
                                                 const float* __restrict__ bh) {
    __shared__ float xs[8 * Dd];
    const int row0 = blockIdx.x * 8;

    const float4* xg = (const float4*)(x + (size_t)row0 * Dd);
    float4* xs4 = (float4*)xs;
    xs4[threadIdx.x] = xg[threadIdx.x];
    xs4[threadIdx.x + 256] = xg[threadIdx.x + 256];
    __syncthreads();

    const int u = threadIdx.x & 31;
    const int which = (threadIdx.x >> 5) & 1;  // warp-uniform: 0 -> q, 1 -> k
    const int rp = threadIdx.x >> 6;           // 0..3
    const float* __restrict__ W = which ? Wx : Wt;

    float acc0 = which ? 0.f : bh[u];
    float acc1 = acc0;
    const float* xr0 = xs + rp * Dd;
    const float* xr1 = xs + (rp + 4) * Dd;

#pragma unroll 8
    for (int d = 0; d < Dd; d++) {
        float w = W[d * Uu + u];
        acc0 = fmaf(xr0[d], w, acc0);
        acc1 = fmaf(xr1[d], w, acc1);
    }

    const float C2LOG2E = 2.8853900817779268f;  // 2*log2(e)
    float* dst = which ? g_k : g_q;
    dst[(row0 + rp) * Uu + u] = fast_ex2(C2LOG2E * acc0);
    dst[(row0 + rp + 4) * Uu + u] = fast_ex2(C2LOG2E * acc1);
}

// ---------------------------------------------------------------------------
// Kernel 2 (fused), 512 threads, TS=16, grid = 256 blocks:
//   A: alpha[s,t] = sumWa - 2*sum_u Wa_u / (1 + Eq[s,u]*Ek[t,u])
//   B: softmax over t (per s row)
//   C: c[s,:] = sum_t a[s,t] * x[b,t,:]  -- thread owns a d-PAIR and all 16 s
//      (16 f32x2 accumulators); 4 t-quarters reduced via smem tree.
// ---------------------------------------------------------------------------
__global__ __launch_bounds__(512, 2) void attn_kernel(const float* __restrict__ x,
                                                      const float* __restrict__ Wa,
                                                      float* __restrict__ out) {
    __shared__ __align__(16) float sa[Ll * PAD];  // 40 KB: weights [t][s] / reduce buf
    __shared__ __align__(16) float sq[TS * Uu];   // 2 KB
    __shared__ float swa[Uu];

    const int tid = threadIdx.x;
    const int b = blockIdx.x >> 5;        // 32 tiles per batch
    const int s0 = (blockIdx.x & 31) * TS;

    sq[tid] = g_q[((size_t)b * Ll + s0) * Uu + tid];  // 512 = TS*Uu exactly
    if (tid < Uu) swa[tid] = Wa[tid];
    __syncthreads();

    // -------- Phase A: thread `tid` owns key row t = tid
    {
        const int t = tid;
        float kk[32];
        const float4* kg = (const float4*)(g_k + ((size_t)b * Ll + t) * Uu);
#pragma unroll
        for (int i = 0; i < 8; i++) {
            float4 kv = kg[i];
            kk[4 * i + 0] = kv.x; kk[4 * i + 1] = kv.y;
            kk[4 * i + 2] = kv.z; kk[4 * i + 3] = kv.w;
        }

        float sumwa = 0.f;
#pragma unroll
        for (int u = 0; u < Uu; u++) sumwa += swa[u];

        const float4* swa4 = (const float4*)swa;

#pragma unroll
        for (int s = 0; s < TS; s++) {
            const float4* eq4 = (const float4*)(sq + s * Uu);
            float acc0 = 0.f, acc1 = 0.f;
#pragma unroll
            for (int i = 0; i < 8; i++) {
                float4 q4 = eq4[i];   // broadcast LDS
                float4 w4 = swa4[i];
                acc0 = fmaf(w4.x, fast_rcp(fmaf(kk[4 * i + 0], q4.x, 1.f)), acc0);
                acc1 = fmaf(w4.y, fast_rcp(fmaf(kk[4 * i + 1], q4.y, 1.f)), acc1);
                acc0 = fmaf(w4.z, fast_rcp(fmaf(kk[4 * i + 2], q4.z, 1.f)), acc0);
                acc1 = fmaf(w4.w, fast_rcp(fmaf(kk[4 * i + 3], q4.w, 1.f)), acc1);
            }
            sa[t * PAD + s] = fmaf(-2.f, acc0 + acc1, sumwa);
        }
    }
    __syncthreads();

    // -------- Phase B: warp w handles softmax of row s = w (16 warps)
    {
        const int w = tid >> 5;
        const int lane = tid & 31;
        const float LOG2E = 1.4426950408889634f;

        float v[16];
        float m = -1e30f;
#pragma unroll
        for (int i = 0; i < 16; i++) {
            v[i] = sa[(lane + 32 * i) * PAD + w];
            m = fmaxf(m, v[i]);
        }
#pragma unroll
        for (int off = 16; off > 0; off >>= 1)
            m = fmaxf(m, __shfl_xor_sync(0xffffffffu, m, off));

        float ssum = 0.f;
#pragma unroll
        for (int i = 0; i < 16; i++) {
            v[i] = fast_ex2((v[i] - m) * LOG2E);
            ssum += v[i];
        }
#pragma unroll
        for (int off = 16; off > 0; off >>= 1)
            ssum += __shfl_xor_sync(0xffffffffu, ssum, off);

        const float inv = fast_rcp(ssum);
#pragma unroll
        for (int i = 0; i < 16; i++) sa[(lane + 32 * i) * PAD + w] = v[i] * inv;
    }
    __syncthreads();

    // -------- Phase C: thread owns d-pair (2 cols) and ALL 16 s;
    //          4 t-quarters, smem tree reduction.
    {
        const int dp = tid & 127;   // d-pair index; d = 2*dp
        const int tq = tid >> 7;    // t-quarter: [128*tq, 128*tq+128)
        const int d = dp * 2;

        // acc[2*jp + dd]: s-pair jp (lanes s=2jp, 2jp+1), column d+dd
        unsigned long long acc[16];
#pragma unroll
        for (int j = 0; j < 16; j++) acc[j] = 0ull;

        const float* __restrict__ xb = x + ((size_t)b * Ll + tq * 128) * Dd + d;
        const float* sp = sa + tq * 128 * PAD;

#pragma unroll 4
        for (int t = 0; t < 128; t++) {
            float2 xv = *(const float2*)(xb + t * Dd);  // coalesced LDG.64
            unsigned long long xx0 = pack2(xv.x, xv.x);
            unsigned long long xx1 = pack2(xv.y, xv.y);

            const float* r = sp + t * PAD;
            // 4 warp-broadcast LDS.128: 16 s weights, reused for both columns
            ulonglong2 p0 = *(const ulonglong2*)(r);       // s-pairs 0,1
            ulonglong2 p1 = *(const ulonglong2*)(r + 4);   // s-pairs 2,3
            ulonglong2 p2 = *(const ulonglong2*)(r + 8);   // s-pairs 4,5
            ulonglong2 p3 = *(const ulonglong2*)(r + 12);  // s-pairs 6,7

            fma2(acc[0],  p0.x, xx0); fma2(acc[1],  p0.x, xx1);
            fma2(acc[2],  p0.y, xx0); fma2(acc[3],  p0.y, xx1);
            fma2(acc[4],  p1.x, xx0); fma2(acc[5],  p1.x, xx1);
            fma2(acc[6],  p1.y, xx0); fma2(acc[7],  p1.y, xx1);
            fma2(acc[8],  p2.x, xx0); fma2(acc[9],  p2.x, xx1);
            fma2(acc[10], p2.y, xx0); fma2(acc[11], p2.y, xx1);
            fma2(acc[12], p3.x, xx0); fma2(acc[13], p3.x, xx1);
            fma2(acc[14], p3.y, xx0); fma2(acc[15], p3.y, xx1);
        }

        __syncthreads();  // all weight reads done; sa reusable as reduce buffer
        unsigned long long* red = (unsigned long long*)sa;

        // step 1: q1 -> buf0, q3 -> buf1;  q0 += buf0, q2 += buf1
        if (tq & 1) {
            unsigned long long* dst = red + ((tq >> 1) * 128 + dp) * RSTRIDE;
#pragma unroll
            for (int j = 0; j < 16; j++) dst[j] = acc[j];
        }
        __syncthreads();
        if (!(tq & 1)) {
            const unsigned long long* src = red + ((tq >> 1) * 128 + dp) * RSTRIDE;
#pragma unroll
            for (int j = 0; j < 16; j++) add2(acc[j], src[j]);
        }
        __syncthreads();

        // step 2: q2 -> buf0; q0 += buf0
        if (tq == 2) {
            unsigned long long* dst = red + dp * RSTRIDE;
#pragma unroll
            for (int j = 0; j < 16; j++) dst[j] = acc[j];
        }
        __syncthreads();
        if (tq == 0) {
            const unsigned long long* src = red + dp * RSTRIDE;
#pragma unroll
            for (int j = 0; j < 16; j++) add2(acc[j], src[j]);

            float* ob = out + ((size_t)b * Ll + s0) * Dd + d;
#pragma unroll
            for (int jp = 0; jp < 8; jp++) {
                float lo0, hi0, lo1, hi1;
                unpack2(lo0, hi0, acc[2 * jp + 0]);  // column d   : s=2jp (lo), 2jp+1 (hi)
                unpack2(lo1, hi1, acc[2 * jp + 1]);  // column d+1
                *(float2*)(ob + (2 * jp + 0) * Dd) = make_float2(lo0, lo1);
                *(float2*)(ob + (2 * jp + 1) * Dd) = make_float2(hi0, hi1);
            }
        }
    }
}

// ---------------------------------------------------------------------------
extern "C" void kernel_launch(void* const* d_in, const int* in_sizes, int n_in,
                              void* d_out, int out_size) {
    const float* x  = (const float*)d_in[0];
    const float* Wt = (const float*)d_in[1];
    const float* Wx = (const float*)d_in[2];
    const float* bh = (const float*)d_in[3];
    const float* Wa = (const float*)d_in[4];
    // d_in[5] = ba: uniform shift of alpha -> softmax-invariant, exactly droppable
    float* out = (float*)d_out;

    qk_kernel<<<Bb * Ll / 8, 256>>>(x, Wt, Wx, bh);
    attn_kernel<<<Bb * (Ll / TS), 512>>>(x, Wa, out);
}